// round 1
// baseline (speedup 1.0000x reference)
#include <cuda_runtime.h>
#include <cuda_bf16.h>

#define Nn   100000
#define Ee   1600000
#define Bb   64
#define DINc 9
#define Hh   128
#define EPSv 1e-5f

// ---------------- device scratch (no allocations allowed) ----------------
__device__ float g_h  [Nn * Hh];
__device__ float g_h2 [Nn * Hh];
__device__ float g_agg[Nn * Hh];
__device__ int   g_deg[Nn];
__device__ int   g_rowptr[Nn + 1];
__device__ int   g_rowfill[Nn];
__device__ int   g_col[Ee];
__device__ int   g_bsum[256];
__device__ float g_psum[Bb * Hh];
__device__ int   g_pmax[Bb * Hh];
__device__ int   g_pcnt[Bb];

// ---------------- init ----------------
__global__ void k_init() {
    int idx = blockIdx.x * blockDim.x + threadIdx.x;
    if (idx < Nn) { g_deg[idx] = 0; g_rowfill[idx] = 0; }
    if (idx < Bb * Hh) { g_psum[idx] = 0.f; g_pmax[idx] = 0; }
    if (idx < Bb) g_pcnt[idx] = 0;
}

// ---------------- CSR build ----------------
__global__ void k_degree(const int* __restrict__ edge) {
    int e = blockIdx.x * blockDim.x + threadIdx.x;
    if (e >= Ee) return;
    atomicAdd(&g_deg[edge[Ee + e]], 1);   // dst
}

__global__ void k_scan1() {   // 1024 threads/block, block-local exclusive scan
    __shared__ int sh[1024];
    int t = threadIdx.x;
    int idx = blockIdx.x * 1024 + t;
    int v = (idx < Nn) ? g_deg[idx] : 0;
    sh[t] = v;
    for (int ofs = 1; ofs < 1024; ofs <<= 1) {
        __syncthreads();
        int add = (t >= ofs) ? sh[t - ofs] : 0;
        __syncthreads();
        sh[t] += add;
    }
    __syncthreads();
    if (idx < Nn) g_rowptr[idx] = sh[t] - v;          // exclusive
    if (t == 1023) g_bsum[blockIdx.x] = sh[1023];     // block total
}

__global__ void k_scan2(int nblk) {   // 1 thread: exclusive scan of block sums
    int run = 0;
    for (int i = 0; i < nblk; i++) { int t = g_bsum[i]; g_bsum[i] = run; run += t; }
}

__global__ void k_scan3() {
    int idx = blockIdx.x * blockDim.x + threadIdx.x;
    if (idx < Nn) g_rowptr[idx] += g_bsum[idx >> 10];
    if (idx == 0) g_rowptr[Nn] = Ee;
}

__global__ void k_fill(const int* __restrict__ edge) {
    int e = blockIdx.x * blockDim.x + threadIdx.x;
    if (e >= Ee) return;
    int d = edge[Ee + e];
    int pos = g_rowptr[d] + atomicAdd(&g_rowfill[d], 1);
    g_col[pos] = edge[e];   // src
}

// ---------------- node embedder: Linear(9->128) + LN + ReLU ----------------
__global__ void k_embed(const float* __restrict__ x, const float* __restrict__ W0,
                        const float* __restrict__ b0, const float* __restrict__ g0,
                        const float* __restrict__ be0) {
    int n = blockIdx.x;
    int o = threadIdx.x;          // 128 threads
    __shared__ float sx[DINc];
    if (o < DINc) sx[o] = x[n * DINc + o];
    __syncthreads();
    float acc = b0[o];
#pragma unroll
    for (int k = 0; k < DINc; k++) acc += W0[o * DINc + k] * sx[k];

    // LayerNorm over 128 lanes (4 warps)
    float s = acc, sq = acc * acc;
#pragma unroll
    for (int ofs = 16; ofs > 0; ofs >>= 1) {
        s  += __shfl_xor_sync(0xffffffffu, s,  ofs);
        sq += __shfl_xor_sync(0xffffffffu, sq, ofs);
    }
    __shared__ float rs[4], rq[4];
    int w = o >> 5, lane = o & 31;
    if (lane == 0) { rs[w] = s; rq[w] = sq; }
    __syncthreads();
    s  = rs[0] + rs[1] + rs[2] + rs[3];
    sq = rq[0] + rq[1] + rq[2] + rq[3];
    float mean = s * (1.f / Hh);
    float var  = sq * (1.f / Hh) - mean * mean;
    float rstd = rsqrtf(var + EPSv);
    float v = (acc - mean) * rstd * g0[o] + be0[o];
    g_h[(size_t)n * Hh + o] = fmaxf(v, 0.f);
}

// ---------------- mean aggregation: warp per dst node ----------------
__global__ void k_agg(const float* __restrict__ h, float* __restrict__ agg) {
    int gw   = (blockIdx.x * blockDim.x + threadIdx.x) >> 5;
    int lane = threadIdx.x & 31;
    if (gw >= Nn) return;
    int beg = g_rowptr[gw], end = g_rowptr[gw + 1];
    float4 acc = make_float4(0.f, 0.f, 0.f, 0.f);
    for (int e = beg; e < end; e++) {
        int s = __ldg(&g_col[e]);
        float4 v = __ldg((const float4*)(h + (size_t)s * Hh) + lane);
        acc.x += v.x; acc.y += v.y; acc.z += v.z; acc.w += v.w;
    }
    float inv = 1.0f / fmaxf((float)(end - beg), 1.0f);
    ((float4*)(agg + (size_t)gw * Hh))[lane] =
        make_float4(acc.x * inv, acc.y * inv, acc.z * inv, acc.w * inv);
}

// ---------------- fused dual GEMM + LN + ReLU ----------------
// out[n][o] = relu(LN( sum_k Wl[o][k]*agg[n][k] + bl[o] + sum_k Wr[o][k]*h[n][k] ))
#define BM     64
#define KC     32
#define WSTR   132     // padded shared stride for weights [k][o]
#define ASTR   68      // padded shared stride for inputs  [k][n]
#define OSTR   132     // padded shared stride for output tile [n][o]

__global__ void __launch_bounds__(256, 2)
k_gemm_ln(const float* __restrict__ A, const float* __restrict__ Hc,
          const float* __restrict__ Wl, const float* __restrict__ bl,
          const float* __restrict__ Wr, const float* __restrict__ gg,
          const float* __restrict__ bb, float* __restrict__ out) {
    extern __shared__ float sm[];
    float* sWl  = sm;                        // KC*WSTR
    float* sWr  = sWl + KC * WSTR;
    float* sA   = sWr + KC * WSTR;           // KC*ASTR
    float* sH   = sA  + KC * ASTR;
    float* sOut = sH  + KC * ASTR;           // BM*OSTR

    int tid = threadIdx.x;
    int tn = tid & 15;      // node group: nodes tn*4 .. tn*4+3
    int to = tid >> 4;      // out group:  outs  to*8 .. to*8+7
    int nb = blockIdx.x * BM;

    float blv[8];
#pragma unroll
    for (int j = 0; j < 8; j++) blv[j] = bl[to * 8 + j];
    float acc[4][8];
#pragma unroll
    for (int i = 0; i < 4; i++)
#pragma unroll
        for (int j = 0; j < 8; j++) acc[i][j] = (i == 0) ? blv[j] : 0.f;

    for (int kc = 0; kc < Hh; kc += KC) {
        // stage weights transposed: sW[k][o] = W[o][kc+k]
#pragma unroll
        for (int t = 0; t < 4; t++) {
            int fi = tid + 256 * t;          // 0..1023
            int o  = fi >> 3;
            int k  = (fi & 7) * 4;
            float4 w = *(const float4*)(Wl + o * Hh + kc + k);
            sWl[(k+0)*WSTR+o] = w.x; sWl[(k+1)*WSTR+o] = w.y;
            sWl[(k+2)*WSTR+o] = w.z; sWl[(k+3)*WSTR+o] = w.w;
            w = *(const float4*)(Wr + o * Hh + kc + k);
            sWr[(k+0)*WSTR+o] = w.x; sWr[(k+1)*WSTR+o] = w.y;
            sWr[(k+2)*WSTR+o] = w.z; sWr[(k+3)*WSTR+o] = w.w;
        }
        // stage inputs transposed: sA[k][n] = A[nb+n][kc+k]
#pragma unroll
        for (int t = 0; t < 2; t++) {
            int fi = tid + 256 * t;          // 0..511
            int n  = fi >> 3;
            int k  = (fi & 7) * 4;
            int gn = nb + n;
            float4 a = (gn < Nn) ? *(const float4*)(A  + (size_t)gn * Hh + kc + k)
                                 : make_float4(0.f, 0.f, 0.f, 0.f);
            sA[(k+0)*ASTR+n] = a.x; sA[(k+1)*ASTR+n] = a.y;
            sA[(k+2)*ASTR+n] = a.z; sA[(k+3)*ASTR+n] = a.w;
            float4 hv = (gn < Nn) ? *(const float4*)(Hc + (size_t)gn * Hh + kc + k)
                                  : make_float4(0.f, 0.f, 0.f, 0.f);
            sH[(k+0)*ASTR+n] = hv.x; sH[(k+1)*ASTR+n] = hv.y;
            sH[(k+2)*ASTR+n] = hv.z; sH[(k+3)*ASTR+n] = hv.w;
        }
        __syncthreads();
#pragma unroll 8
        for (int k = 0; k < KC; k++) {
            float4 av  = *(const float4*)(sA  + k * ASTR + tn * 4);
            float4 hv  = *(const float4*)(sH  + k * ASTR + tn * 4);
            float4 wl0 = *(const float4*)(sWl + k * WSTR + to * 8);
            float4 wl1 = *(const float4*)(sWl + k * WSTR + to * 8 + 4);
            float4 wr0 = *(const float4*)(sWr + k * WSTR + to * 8);
            float4 wr1 = *(const float4*)(sWr + k * WSTR + to * 8 + 4);
            float a_[4] = {av.x, av.y, av.z, av.w};
            float h_[4] = {hv.x, hv.y, hv.z, hv.w};
            float wlv[8] = {wl0.x, wl0.y, wl0.z, wl0.w, wl1.x, wl1.y, wl1.z, wl1.w};
            float wrv[8] = {wr0.x, wr0.y, wr0.z, wr0.w, wr1.x, wr1.y, wr1.z, wr1.w};
#pragma unroll
            for (int i = 0; i < 4; i++)
#pragma unroll
                for (int j = 0; j < 8; j++)
                    acc[i][j] += wlv[j] * a_[i] + wrv[j] * h_[i];
        }
        __syncthreads();
    }

    // dump to shared output tile
#pragma unroll
    for (int i = 0; i < 4; i++) {
        *(float4*)(sOut + (tn*4+i)*OSTR + to*8)     = make_float4(acc[i][0], acc[i][1], acc[i][2], acc[i][3]);
        *(float4*)(sOut + (tn*4+i)*OSTR + to*8 + 4) = make_float4(acc[i][4], acc[i][5], acc[i][6], acc[i][7]);
    }
    __syncthreads();

    // LayerNorm + ReLU: warp per node
    int lane = tid & 31, w = tid >> 5;
    for (int nrow = w; nrow < BM; nrow += 8) {
        int gn = nb + nrow;
        if (gn >= Nn) continue;
        float4 v = *(const float4*)(sOut + nrow * OSTR + lane * 4);
        float s  = v.x + v.y + v.z + v.w;
        float sq = v.x*v.x + v.y*v.y + v.z*v.z + v.w*v.w;
#pragma unroll
        for (int ofs = 16; ofs > 0; ofs >>= 1) {
            s  += __shfl_xor_sync(0xffffffffu, s,  ofs);
            sq += __shfl_xor_sync(0xffffffffu, sq, ofs);
        }
        float mean = s * (1.f / Hh);
        float var  = sq * (1.f / Hh) - mean * mean;
        float rstd = rsqrtf(var + EPSv);
        float4 gv = *(const float4*)(gg + lane * 4);
        float4 bv = *(const float4*)(bb + lane * 4);
        float4 r;
        r.x = fmaxf((v.x - mean) * rstd * gv.x + bv.x, 0.f);
        r.y = fmaxf((v.y - mean) * rstd * gv.y + bv.y, 0.f);
        r.z = fmaxf((v.z - mean) * rstd * gv.z + bv.z, 0.f);
        r.w = fmaxf((v.w - mean) * rstd * gv.w + bv.w, 0.f);
        *(float4*)(out + (size_t)gn * Hh + lane * 4) = r;
    }
}

// ---------------- pooling (batch is sorted -> run-length local accumulate) ----------------
#define PT 256
__global__ void k_pool(const float* __restrict__ ne, const int* __restrict__ batch) {
    __shared__ int sb[PT];
    int c = threadIdx.x;                 // 128 = channel
    int start = blockIdx.x * PT;
    int cnt_nodes = min(PT, Nn - start);
    for (int i = c; i < cnt_nodes; i += 128) sb[i] = batch[start + i];
    __syncthreads();
    float s = 0.f, mx = 0.f; int cnt = 0;
    int curb = sb[0];
    for (int i = 0; i < cnt_nodes; i++) {
        int b = sb[i];
        if (b != curb) {
            atomicAdd(&g_psum[curb * Hh + c], s);
            atomicMax(&g_pmax[curb * Hh + c], __float_as_int(mx));
            if (c == 0) atomicAdd(&g_pcnt[curb], cnt);
            s = 0.f; mx = 0.f; cnt = 0; curb = b;
        }
        float v = ne[(size_t)(start + i) * Hh + c];
        s += v; mx = fmaxf(mx, v); cnt++;
    }
    atomicAdd(&g_psum[curb * Hh + c], s);
    atomicMax(&g_pmax[curb * Hh + c], __float_as_int(mx));
    if (c == 0) atomicAdd(&g_pcnt[curb], cnt);
}

__global__ void k_pool_fin(float* __restrict__ out) {
    int idx = blockIdx.x * blockDim.x + threadIdx.x;
    if (idx >= Bb * Hh) return;
    int b = idx >> 7, c = idx & 127;
    float cnt = fmaxf((float)g_pcnt[b], 1.f);
    out[(size_t)Nn * Hh + b * 2 * Hh + c]      = g_psum[idx] / cnt;
    out[(size_t)Nn * Hh + b * 2 * Hh + Hh + c] = __int_as_float(g_pmax[idx]);
}

// ---------------- launch ----------------
extern "C" void kernel_launch(void* const* d_in, const int* in_sizes, int n_in,
                              void* d_out, int out_size) {
    const float* x    = (const float*)d_in[0];
    const int*   edge = (const int*)  d_in[1];
    const int*   batch= (const int*)  d_in[2];
    const float* W0   = (const float*)d_in[3];
    const float* b0   = (const float*)d_in[4];
    const float* g0   = (const float*)d_in[5];
    const float* be0  = (const float*)d_in[6];
    const float* Wl1  = (const float*)d_in[7];
    const float* bl1  = (const float*)d_in[8];
    const float* Wr1  = (const float*)d_in[9];
    const float* g1   = (const float*)d_in[10];
    const float* be1  = (const float*)d_in[11];
    const float* Wl2  = (const float*)d_in[12];
    const float* bl2  = (const float*)d_in[13];
    const float* Wr2  = (const float*)d_in[14];
    const float* g2   = (const float*)d_in[15];
    const float* be2  = (const float*)d_in[16];
    const float* Wl3  = (const float*)d_in[17];
    const float* bl3  = (const float*)d_in[18];
    const float* Wr3  = (const float*)d_in[19];
    const float* g3   = (const float*)d_in[20];
    const float* be3  = (const float*)d_in[21];
    float* out = (float*)d_out;

    static int smem_set = 0;
    const int GEMM_SMEM = (2 * KC * WSTR + 2 * KC * ASTR + BM * OSTR) * 4;
    if (!smem_set) {
        cudaFuncSetAttribute(k_gemm_ln, cudaFuncAttributeMaxDynamicSharedMemorySize, GEMM_SMEM);
        smem_set = 1;
    }

    float *h_cur, *h_nxt, *agg;
    cudaGetSymbolAddress((void**)&h_cur, g_h);     // resolved at capture time (host API, fine)
    cudaGetSymbolAddress((void**)&h_nxt, g_h2);
    cudaGetSymbolAddress((void**)&agg,   g_agg);

    int nblkScan = (Nn + 1023) / 1024;

    k_init  <<<(Nn + 255) / 256, 256>>>();
    k_degree<<<(Ee + 255) / 256, 256>>>(edge);
    k_scan1 <<<nblkScan, 1024>>>();
    k_scan2 <<<1, 1>>>(nblkScan);
    k_scan3 <<<(Nn + 255) / 256, 256>>>();
    k_fill  <<<(Ee + 255) / 256, 256>>>(edge);

    k_embed <<<Nn, 128>>>(x, W0, b0, g0, be0);

    int gemmGrid = (Nn + BM - 1) / BM;
    int aggGrid  = (Nn * 32 + 255) / 256;

    // layer 1: g_h -> g_h2
    k_agg    <<<aggGrid, 256>>>(h_cur, agg);
    k_gemm_ln<<<gemmGrid, 256, GEMM_SMEM>>>(agg, h_cur, Wl1, bl1, Wr1, g1, be1, h_nxt);
    // layer 2: g_h2 -> g_h
    k_agg    <<<aggGrid, 256>>>(h_nxt, agg);
    k_gemm_ln<<<gemmGrid, 256, GEMM_SMEM>>>(agg, h_nxt, Wl2, bl2, Wr2, g2, be2, h_cur);
    // layer 3: g_h -> node_embed (start of d_out)
    k_agg    <<<aggGrid, 256>>>(h_cur, agg);
    k_gemm_ln<<<gemmGrid, 256, GEMM_SMEM>>>(agg, h_cur, Wl3, bl3, Wr3, g3, be3, out);

    k_pool    <<<(Nn + PT - 1) / PT, 128>>>(out, batch);
    k_pool_fin<<<(Bb * Hh + 127) / 128, 128>>>(out);
}

// round 5
// speedup vs baseline: 1.5423x; 1.5423x over previous
#include <cuda_runtime.h>
#include <cuda_bf16.h>
#include <cstdint>

#define Nn   100000
#define Ee   1600000
#define Bb   64
#define DINc 9
#define Hh   128
#define EPSv 1e-5f

// ---------------- device scratch ----------------
__device__ float g_h  [Nn * Hh];
__device__ float g_h2 [Nn * Hh];
__device__ __nv_bfloat16 g_hs_hi0[Nn * Hh];
__device__ __nv_bfloat16 g_hs_lo0[Nn * Hh];
__device__ __nv_bfloat16 g_hs_hi1[Nn * Hh];
__device__ __nv_bfloat16 g_hs_lo1[Nn * Hh];
__device__ __nv_bfloat16 g_ag_hi[Nn * Hh];
__device__ __nv_bfloat16 g_ag_lo[Nn * Hh];
__device__ uint4 g_wfrag[16 * 16 * 32];     // [ntile][kstep][lane] -> (bh0,bh1,bl0,bl1)
__device__ int   g_deg[Nn];
__device__ int   g_rowptr[Nn + 1];
__device__ int   g_rowfill[Nn];
__device__ int   g_col[Ee];
__device__ int   g_bsum[256];
__device__ float g_psum[Bb * Hh];
__device__ int   g_pmax[Bb * Hh];
__device__ int   g_pcnt[Bb];

// ---------------- helpers ----------------
__device__ __forceinline__ uint32_t pack_bf16(__nv_bfloat16 a, __nv_bfloat16 b) {
    return (uint32_t)__bfloat16_as_ushort(a) | ((uint32_t)__bfloat16_as_ushort(b) << 16);
}
__device__ __forceinline__ void mma16816(float* d, const uint32_t* a, uint32_t b0, uint32_t b1) {
    asm volatile("mma.sync.aligned.m16n8k16.row.col.f32.bf16.bf16.f32 "
        "{%0,%1,%2,%3}, {%4,%5,%6,%7}, {%8,%9}, {%0,%1,%2,%3};"
        : "+f"(d[0]), "+f"(d[1]), "+f"(d[2]), "+f"(d[3])
        : "r"(a[0]), "r"(a[1]), "r"(a[2]), "r"(a[3]), "r"(b0), "r"(b1));
}

// ---------------- init ----------------
__global__ void k_init() {
    int idx = blockIdx.x * blockDim.x + threadIdx.x;
    if (idx < Nn) { g_deg[idx] = 0; g_rowfill[idx] = 0; }
    if (idx < Bb * Hh) { g_psum[idx] = 0.f; g_pmax[idx] = 0; }
    if (idx < Bb) g_pcnt[idx] = 0;
}

// ---------------- CSR build ----------------
__global__ void k_degree(const int* __restrict__ edge) {
    int e = blockIdx.x * blockDim.x + threadIdx.x;
    if (e >= Ee) return;
    atomicAdd(&g_deg[edge[Ee + e]], 1);
}

__global__ void k_scan1() {
    __shared__ int sh[1024];
    int t = threadIdx.x;
    int idx = blockIdx.x * 1024 + t;
    int v = (idx < Nn) ? g_deg[idx] : 0;
    sh[t] = v;
    for (int ofs = 1; ofs < 1024; ofs <<= 1) {
        __syncthreads();
        int add = (t >= ofs) ? sh[t - ofs] : 0;
        __syncthreads();
        sh[t] += add;
    }
    __syncthreads();
    if (idx < Nn) g_rowptr[idx] = sh[t] - v;
    if (t == 1023) g_bsum[blockIdx.x] = sh[1023];
}

__global__ void k_scan2(int nblk) {   // 128 threads, nblk <= 128
    __shared__ int sh[128];
    int t = threadIdx.x;
    int v = (t < nblk) ? g_bsum[t] : 0;
    sh[t] = v;
    for (int ofs = 1; ofs < 128; ofs <<= 1) {
        __syncthreads();
        int add = (t >= ofs) ? sh[t - ofs] : 0;
        __syncthreads();
        sh[t] += add;
    }
    __syncthreads();
    if (t < nblk) g_bsum[t] = sh[t] - v;
}

__global__ void k_scan3() {
    int idx = blockIdx.x * blockDim.x + threadIdx.x;
    if (idx < Nn) g_rowptr[idx] += g_bsum[idx >> 10];
    if (idx == 0) g_rowptr[Nn] = Ee;
}

__global__ void k_fill(const int* __restrict__ edge) {
    int e = blockIdx.x * blockDim.x + threadIdx.x;
    if (e >= Ee) return;
    int d = edge[Ee + e];
    int pos = g_rowptr[d] + atomicAdd(&g_rowfill[d], 1);
    g_col[pos] = edge[e];
}

// ---------------- node embedder: Linear(9->128) + LN + ReLU + split ----------------
__global__ void k_embed(const float* __restrict__ x, const float* __restrict__ W0,
                        const float* __restrict__ b0, const float* __restrict__ g0,
                        const float* __restrict__ be0) {
    int n = blockIdx.x;
    int o = threadIdx.x;
    __shared__ float sx[DINc];
    if (o < DINc) sx[o] = x[n * DINc + o];
    __syncthreads();
    float acc = b0[o];
#pragma unroll
    for (int k = 0; k < DINc; k++) acc += W0[o * DINc + k] * sx[k];

    float s = acc, sq = acc * acc;
#pragma unroll
    for (int ofs = 16; ofs > 0; ofs >>= 1) {
        s  += __shfl_xor_sync(0xffffffffu, s,  ofs);
        sq += __shfl_xor_sync(0xffffffffu, sq, ofs);
    }
    __shared__ float rs[4], rq[4];
    int w = o >> 5, lane = o & 31;
    if (lane == 0) { rs[w] = s; rq[w] = sq; }
    __syncthreads();
    s  = rs[0] + rs[1] + rs[2] + rs[3];
    sq = rq[0] + rq[1] + rq[2] + rq[3];
    float mean = s * (1.f / Hh);
    float var  = sq * (1.f / Hh) - mean * mean;
    float rstd = rsqrtf(var + EPSv);
    float v = (acc - mean) * rstd * g0[o] + be0[o];
    float r = fmaxf(v, 0.f);
    size_t idx = (size_t)n * Hh + o;
    g_h[idx] = r;
    __nv_bfloat16 hb = __float2bfloat16(r);
    g_hs_hi0[idx] = hb;
    g_hs_lo0[idx] = __float2bfloat16(r - __bfloat162float(hb));
}

// ---------------- mean aggregation: warp per dst node, writes bf16 splits ----------------
__global__ void k_agg(const float* __restrict__ h) {
    int gw   = (blockIdx.x * blockDim.x + threadIdx.x) >> 5;
    int lane = threadIdx.x & 31;
    if (gw >= Nn) return;
    int beg = g_rowptr[gw], end = g_rowptr[gw + 1];
    float4 acc = make_float4(0.f, 0.f, 0.f, 0.f);
    for (int e = beg; e < end; e++) {
        int s = __ldg(&g_col[e]);
        float4 v = __ldg((const float4*)(h + (size_t)s * Hh) + lane);
        acc.x += v.x; acc.y += v.y; acc.z += v.z; acc.w += v.w;
    }
    float inv = 1.0f / fmaxf((float)(end - beg), 1.0f);
    float r0 = acc.x * inv, r1 = acc.y * inv, r2 = acc.z * inv, r3 = acc.w * inv;
    __nv_bfloat16 h0 = __float2bfloat16(r0), h1 = __float2bfloat16(r1);
    __nv_bfloat16 h2 = __float2bfloat16(r2), h3 = __float2bfloat16(r3);
    uint2 qh, ql;
    qh.x = pack_bf16(h0, h1);
    qh.y = pack_bf16(h2, h3);
    ql.x = pack_bf16(__float2bfloat16(r0 - __bfloat162float(h0)),
                     __float2bfloat16(r1 - __bfloat162float(h1)));
    ql.y = pack_bf16(__float2bfloat16(r2 - __bfloat162float(h2)),
                     __float2bfloat16(r3 - __bfloat162float(h3)));
    ((uint2*)(g_ag_hi + (size_t)gw * Hh))[lane] = qh;
    ((uint2*)(g_ag_lo + (size_t)gw * Hh))[lane] = ql;
}

// ---------------- weight prep: [Wl | Wr] (K=256) -> mma B-fragment layout ----------------
// fragment (m16n8k16 B): lane l, n = ntile*8 + (l>>2);
//   b0 = W[n][kstep*16 + 2(l&3)], W[n][.. + 1]; b1 = same + 8
__global__ void k_prepw(const float* __restrict__ Wl, const float* __restrict__ Wr) {
    int idx = blockIdx.x * blockDim.x + threadIdx.x;   // 8192
    if (idx >= 16 * 16 * 32) return;
    int lane = idx & 31, ks = (idx >> 5) & 15, nt = idx >> 9;
    int o = nt * 8 + (lane >> 2);
    int kb = ks * 16 + 2 * (lane & 3);
    float v[4];
#pragma unroll
    for (int j = 0; j < 4; j++) {
        int k = kb + (j >> 1) * 8 + (j & 1);   // k0,k0+1,k0+8,k0+9
        v[j] = (k < Hh) ? Wl[o * Hh + k] : Wr[o * Hh + (k - Hh)];
    }
    __nv_bfloat16 hb[4]; __nv_bfloat16 lb[4];
#pragma unroll
    for (int j = 0; j < 4; j++) {
        hb[j] = __float2bfloat16(v[j]);
        lb[j] = __float2bfloat16(v[j] - __bfloat162float(hb[j]));
    }
    uint4 q;
    q.x = pack_bf16(hb[0], hb[1]);
    q.y = pack_bf16(hb[2], hb[3]);
    q.z = pack_bf16(lb[0], lb[1]);
    q.w = pack_bf16(lb[2], lb[3]);
    g_wfrag[idx] = q;
}

// ---------------- mma.sync fused dual GEMM + LN + ReLU ----------------
// out[n][o] = relu(LN( [agg(n);h(n)](K=256) . W[o] + bl[o] ))   split-bf16 x3
#define SB_U4   (16 * 16 * 32)
#define GSMEM   (SB_U4 * 16 + 3 * 512)

__global__ void __launch_bounds__(256, 1)
k_gemm_mma(const __nv_bfloat16* __restrict__ ag_hi, const __nv_bfloat16* __restrict__ ag_lo,
           const __nv_bfloat16* __restrict__ h_hi,  const __nv_bfloat16* __restrict__ h_lo,
           const float* __restrict__ bl, const float* __restrict__ gg,
           const float* __restrict__ bb, float* __restrict__ out,
           __nv_bfloat16* __restrict__ o_hi, __nv_bfloat16* __restrict__ o_lo,
           int write_split)
{
    extern __shared__ char smc[];
    uint4* sB    = (uint4*)smc;                       // 8192 uint4 = 128 KB
    float* sBias = (float*)(smc + SB_U4 * 16);
    float* sG    = sBias + 128;
    float* sBb   = sG + 128;

    int tid = threadIdx.x, lane = tid & 31, warp = tid >> 5;
    int nb = blockIdx.x * 128;

#pragma unroll
    for (int i = 0; i < 32; i++) sB[tid + i * 256] = g_wfrag[tid + i * 256];
    if (tid < 128) { sBias[tid] = bl[tid]; sG[tid] = gg[tid]; sBb[tid] = bb[tid]; }
    __syncthreads();

    int r0    = warp * 16 + (lane >> 2);
    int grow0 = nb + r0, grow1 = grow0 + 8;
    bool v0 = grow0 < Nn, v1 = grow1 < Nn;
    int kcol = 2 * (lane & 3);

    float acc[16][4];
#pragma unroll
    for (int nt = 0; nt < 16; nt++) {
        acc[nt][0] = 0.f; acc[nt][1] = 0.f; acc[nt][2] = 0.f; acc[nt][3] = 0.f;
    }

#pragma unroll 4
    for (int ks = 0; ks < 16; ks++) {
        const __nv_bfloat16* ph = (ks < 8) ? ag_hi : h_hi;
        const __nv_bfloat16* pl = (ks < 8) ? ag_lo : h_lo;
        int ko = (ks & 7) * 16 + kcol;
        size_t o0 = (size_t)grow0 * Hh + ko;
        size_t o1 = (size_t)grow1 * Hh + ko;
        uint32_t ah[4], al[4];
        ah[0] = v0 ? *(const uint32_t*)(ph + o0)     : 0u;
        ah[1] = v1 ? *(const uint32_t*)(ph + o1)     : 0u;
        ah[2] = v0 ? *(const uint32_t*)(ph + o0 + 8) : 0u;
        ah[3] = v1 ? *(const uint32_t*)(ph + o1 + 8) : 0u;
        al[0] = v0 ? *(const uint32_t*)(pl + o0)     : 0u;
        al[1] = v1 ? *(const uint32_t*)(pl + o1)     : 0u;
        al[2] = v0 ? *(const uint32_t*)(pl + o0 + 8) : 0u;
        al[3] = v1 ? *(const uint32_t*)(pl + o1 + 8) : 0u;
        const uint4* brow = sB + ks * 32 + lane;
#pragma unroll
        for (int nt = 0; nt < 16; nt++) {
            uint4 b = brow[nt * 512];
            mma16816(acc[nt], ah, b.x, b.y);   // Ah * Wh
            mma16816(acc[nt], al, b.x, b.y);   // Al * Wh
            mma16816(acc[nt], ah, b.z, b.w);   // Ah * Wl
        }
    }

    // ---- epilogue: bias + LN + ReLU ----
    float s0 = 0.f, q0 = 0.f, s1 = 0.f, q1 = 0.f;
#pragma unroll
    for (int nt = 0; nt < 16; nt++) {
        int c = nt * 8 + kcol;
        float b0v = sBias[c], b1v = sBias[c + 1];
        acc[nt][0] += b0v; acc[nt][1] += b1v;
        acc[nt][2] += b0v; acc[nt][3] += b1v;
        s0 += acc[nt][0] + acc[nt][1];
        q0 += acc[nt][0] * acc[nt][0] + acc[nt][1] * acc[nt][1];
        s1 += acc[nt][2] + acc[nt][3];
        q1 += acc[nt][2] * acc[nt][2] + acc[nt][3] * acc[nt][3];
    }
#pragma unroll
    for (int ofs = 1; ofs <= 2; ofs <<= 1) {
        s0 += __shfl_xor_sync(0xffffffffu, s0, ofs);
        q0 += __shfl_xor_sync(0xffffffffu, q0, ofs);
        s1 += __shfl_xor_sync(0xffffffffu, s1, ofs);
        q1 += __shfl_xor_sync(0xffffffffu, q1, ofs);
    }
    float mean0 = s0 * (1.f / Hh);
    float var0  = q0 * (1.f / Hh) - mean0 * mean0;
    float rstd0 = rsqrtf(var0 + EPSv);
    float mean1 = s1 * (1.f / Hh);
    float var1  = q1 * (1.f / Hh) - mean1 * mean1;
    float rstd1 = rsqrtf(var1 + EPSv);

#pragma unroll
    for (int nt = 0; nt < 16; nt++) {
        int c = nt * 8 + kcol;
        float gc0 = sG[c], gc1 = sG[c + 1], bc0 = sBb[c], bc1 = sBb[c + 1];
        float w0 = fmaxf((acc[nt][0] - mean0) * rstd0 * gc0 + bc0, 0.f);
        float w1 = fmaxf((acc[nt][1] - mean0) * rstd0 * gc1 + bc1, 0.f);
        float w2 = fmaxf((acc[nt][2] - mean1) * rstd1 * gc0 + bc0, 0.f);
        float w3 = fmaxf((acc[nt][3] - mean1) * rstd1 * gc1 + bc1, 0.f);
        if (v0) *(float2*)(out + (size_t)grow0 * Hh + c) = make_float2(w0, w1);
        if (v1) *(float2*)(out + (size_t)grow1 * Hh + c) = make_float2(w2, w3);
        if (write_split) {
            if (v0) {
                __nv_bfloat16 h0 = __float2bfloat16(w0), h1 = __float2bfloat16(w1);
                *(uint32_t*)(o_hi + (size_t)grow0 * Hh + c) = pack_bf16(h0, h1);
                *(uint32_t*)(o_lo + (size_t)grow0 * Hh + c) =
                    pack_bf16(__float2bfloat16(w0 - __bfloat162float(h0)),
                              __float2bfloat16(w1 - __bfloat162float(h1)));
            }
            if (v1) {
                __nv_bfloat16 h2 = __float2bfloat16(w2), h3 = __float2bfloat16(w3);
                *(uint32_t*)(o_hi + (size_t)grow1 * Hh + c) = pack_bf16(h2, h3);
                *(uint32_t*)(o_lo + (size_t)grow1 * Hh + c) =
                    pack_bf16(__float2bfloat16(w2 - __bfloat162float(h2)),
                              __float2bfloat16(w3 - __bfloat162float(h3)));
            }
        }
    }
}

// ---------------- pooling ----------------
#define PT 256
__global__ void k_pool(const float* __restrict__ ne, const int* __restrict__ batch) {
    __shared__ int sbk[PT];
    int c = threadIdx.x;
    int start = blockIdx.x * PT;
    int cnt_nodes = min(PT, Nn - start);
    for (int i = c; i < cnt_nodes; i += 128) sbk[i] = batch[start + i];
    __syncthreads();
    float s = 0.f, mx = 0.f; int cnt = 0;
    int curb = sbk[0];
    for (int i = 0; i < cnt_nodes; i++) {
        int b = sbk[i];
        if (b != curb) {
            atomicAdd(&g_psum[curb * Hh + c], s);
            atomicMax(&g_pmax[curb * Hh + c], __float_as_int(mx));
            if (c == 0) atomicAdd(&g_pcnt[curb], cnt);
            s = 0.f; mx = 0.f; cnt = 0; curb = b;
        }
        float v = ne[(size_t)(start + i) * Hh + c];
        s += v; mx = fmaxf(mx, v); cnt++;
    }
    atomicAdd(&g_psum[curb * Hh + c], s);
    atomicMax(&g_pmax[curb * Hh + c], __float_as_int(mx));
    if (c == 0) atomicAdd(&g_pcnt[curb], cnt);
}

__global__ void k_pool_fin(float* __restrict__ out) {
    int idx = blockIdx.x * blockDim.x + threadIdx.x;
    if (idx >= Bb * Hh) return;
    int b = idx >> 7, c = idx & 127;
    float cnt = fmaxf((float)g_pcnt[b], 1.f);
    out[(size_t)Nn * Hh + b * 2 * Hh + c]      = g_psum[idx] / cnt;
    out[(size_t)Nn * Hh + b * 2 * Hh + Hh + c] = __int_as_float(g_pmax[idx]);
}

// ---------------- launch ----------------
extern "C" void kernel_launch(void* const* d_in, const int* in_sizes, int n_in,
                              void* d_out, int out_size) {
    const float* x    = (const float*)d_in[0];
    const int*   edge = (const int*)  d_in[1];
    const int*   batch= (const int*)  d_in[2];
    const float* W0   = (const float*)d_in[3];
    const float* b0   = (const float*)d_in[4];
    const float* g0   = (const float*)d_in[5];
    const float* be0  = (const float*)d_in[6];
    const float* Wl1  = (const float*)d_in[7];
    const float* bl1  = (const float*)d_in[8];
    const float* Wr1  = (const float*)d_in[9];
    const float* g1   = (const float*)d_in[10];
    const float* be1  = (const float*)d_in[11];
    const float* Wl2  = (const float*)d_in[12];
    const float* bl2  = (const float*)d_in[13];
    const float* Wr2  = (const float*)d_in[14];
    const float* g2   = (const float*)d_in[15];
    const float* be2  = (const float*)d_in[16];
    const float* Wl3  = (const float*)d_in[17];
    const float* bl3  = (const float*)d_in[18];
    const float* Wr3  = (const float*)d_in[19];
    const float* g3   = (const float*)d_in[20];
    const float* be3  = (const float*)d_in[21];
    float* out = (float*)d_out;

    static int attr_set = 0;
    if (!attr_set) {
        cudaFuncSetAttribute(k_gemm_mma, cudaFuncAttributeMaxDynamicSharedMemorySize, GSMEM);
        attr_set = 1;
    }

    float* hA = 0;
    float* hB = 0;
    __nv_bfloat16* aghi = 0;
    __nv_bfloat16* aglo = 0;
    __nv_bfloat16* hi0 = 0;
    __nv_bfloat16* lo0 = 0;
    __nv_bfloat16* hi1 = 0;
    __nv_bfloat16* lo1 = 0;
    cudaGetSymbolAddress((void**)&hA, g_h);
    cudaGetSymbolAddress((void**)&hB, g_h2);
    cudaGetSymbolAddress((void**)&aghi, g_ag_hi);
    cudaGetSymbolAddress((void**)&aglo, g_ag_lo);
    cudaGetSymbolAddress((void**)&hi0, g_hs_hi0);
    cudaGetSymbolAddress((void**)&lo0, g_hs_lo0);
    cudaGetSymbolAddress((void**)&hi1, g_hs_hi1);
    cudaGetSymbolAddress((void**)&lo1, g_hs_lo1);

    int nblkScan = (Nn + 1023) / 1024;

    k_init  <<<(Nn + 255) / 256, 256>>>();
    k_degree<<<(Ee + 255) / 256, 256>>>(edge);
    k_scan1 <<<nblkScan, 1024>>>();
    k_scan2 <<<1, 128>>>(nblkScan);
    k_scan3 <<<(Nn + 255) / 256, 256>>>();
    k_fill  <<<(Ee + 255) / 256, 256>>>(edge);

    k_embed <<<Nn, 128>>>(x, W0, b0, g0, be0);

    int gemmGrid = (Nn + 127) / 128;
    int aggGrid  = (Nn * 32 + 255) / 256;
    int prepGrid = (16 * 16 * 32 + 255) / 256;

    // layer 1: hA -> hB  (splits set0 -> set1)
    k_agg   <<<aggGrid, 256>>>(hA);
    k_prepw <<<prepGrid, 256>>>(Wl1, Wr1);
    k_gemm_mma<<<gemmGrid, 256, GSMEM>>>(aghi, aglo, hi0, lo0,
                                         bl1, g1, be1, hB, hi1, lo1, 1);
    // layer 2: hB -> hA  (splits set1 -> set0)
    k_agg   <<<aggGrid, 256>>>(hB);
    k_prepw <<<prepGrid, 256>>>(Wl2, Wr2);
    k_gemm_mma<<<gemmGrid, 256, GSMEM>>>(aghi, aglo, hi1, lo1,
                                         bl2, g2, be2, hA, hi0, lo0, 1);
    // layer 3: hA -> out (no split needed)
    k_agg   <<<aggGrid, 256>>>(hA);
    k_prepw <<<prepGrid, 256>>>(Wl3, Wr3);
    k_gemm_mma<<<gemmGrid, 256, GSMEM>>>(aghi, aglo, hi0, lo0,
                                         bl3, g3, be3, out,
                                         (__nv_bfloat16*)0, (__nv_bfloat16*)0, 0);

    k_pool    <<<(Nn + PT - 1) / PT, 128>>>(out, batch);
    k_pool_fin<<<(Bb * Hh + 127) / 128, 128>>>(out);
}

// round 6
// speedup vs baseline: 1.6715x; 1.0838x over previous
#include <cuda_runtime.h>
#include <cuda_bf16.h>
#include <cstdint>

#define Nn   100000
#define Ee   1600000
#define Bb   64
#define DINc 9
#define Hh   128
#define EPSv 1e-5f

// ---------------- device scratch ----------------
__device__ float    g_h  [Nn * Hh];      // fp32 features (agg gather source)
__device__ float    g_h2 [Nn * Hh];
__device__ uint32_t g_hp0[Nn * Hh];      // packed (bf16hi<<16)|bf16lo
__device__ uint32_t g_hp1[Nn * Hh];
__device__ uint32_t g_agp[Nn * Hh];      // packed aggregated
__device__ uint4    g_wfrag[3 * 8192];   // per-layer mma B fragments
__device__ int      g_deg[Nn];
__device__ int      g_rowptr[Nn + 1];
__device__ int      g_rowfill[Nn];
__device__ int      g_col[Ee];
__device__ int      g_bsum[128];
__device__ float    g_psum[Bb * Hh];
__device__ int      g_pmax[Bb * Hh];
__device__ int      g_pcnt[Bb];

// ---------------- helpers ----------------
__device__ __forceinline__ uint32_t packf(float v) {
    __nv_bfloat16 hb = __float2bfloat16(v);
    __nv_bfloat16 lb = __float2bfloat16(v - __bfloat162float(hb));
    return ((uint32_t)__bfloat16_as_ushort(hb) << 16) | (uint32_t)__bfloat16_as_ushort(lb);
}
__device__ __forceinline__ uint32_t pack_bf16(__nv_bfloat16 a, __nv_bfloat16 b) {
    return (uint32_t)__bfloat16_as_ushort(a) | ((uint32_t)__bfloat16_as_ushort(b) << 16);
}
__device__ __forceinline__ void mma16816(float* d, const uint32_t* a, uint32_t b0, uint32_t b1) {
    asm volatile("mma.sync.aligned.m16n8k16.row.col.f32.bf16.bf16.f32 "
        "{%0,%1,%2,%3}, {%4,%5,%6,%7}, {%8,%9}, {%0,%1,%2,%3};"
        : "+f"(d[0]), "+f"(d[1]), "+f"(d[2]), "+f"(d[3])
        : "r"(a[0]), "r"(a[1]), "r"(a[2]), "r"(a[3]), "r"(b0), "r"(b1));
}

// ---------------- node embedder (+ global init fused) ----------------
__global__ void k_embed(const float* __restrict__ x, const float* __restrict__ W0,
                        const float* __restrict__ b0, const float* __restrict__ g0,
                        const float* __restrict__ be0, uint32_t* __restrict__ hp) {
    int n = blockIdx.x;
    int o = threadIdx.x;
    int gid = n * 128 + o;
    if (gid < Nn) { g_deg[gid] = 0; g_rowfill[gid] = 0; }
    if (gid < Bb * Hh) { g_psum[gid] = 0.f; g_pmax[gid] = 0; }
    if (gid < Bb) g_pcnt[gid] = 0;

    __shared__ float sx[DINc];
    if (o < DINc) sx[o] = x[n * DINc + o];
    __syncthreads();
    float acc = b0[o];
#pragma unroll
    for (int k = 0; k < DINc; k++) acc += W0[o * DINc + k] * sx[k];

    float s = acc, sq = acc * acc;
#pragma unroll
    for (int ofs = 16; ofs > 0; ofs >>= 1) {
        s  += __shfl_xor_sync(0xffffffffu, s,  ofs);
        sq += __shfl_xor_sync(0xffffffffu, sq, ofs);
    }
    __shared__ float rs[4], rq[4];
    int w = o >> 5, lane = o & 31;
    if (lane == 0) { rs[w] = s; rq[w] = sq; }
    __syncthreads();
    s  = rs[0] + rs[1] + rs[2] + rs[3];
    sq = rq[0] + rq[1] + rq[2] + rq[3];
    float mean = s * (1.f / Hh);
    float var  = sq * (1.f / Hh) - mean * mean;
    float rstd = rsqrtf(var + EPSv);
    float v = (acc - mean) * rstd * g0[o] + be0[o];
    float r = fmaxf(v, 0.f);
    size_t idx = (size_t)n * Hh + o;
    g_h[idx] = r;
    hp[idx] = packf(r);
}

// ---------------- CSR build ----------------
__global__ void k_degree(const int* __restrict__ edge) {
    int e = blockIdx.x * blockDim.x + threadIdx.x;
    if (e >= Ee) return;
    atomicAdd(&g_deg[edge[Ee + e]], 1);
}

__global__ void k_scan1() {
    __shared__ int sh[1024];
    int t = threadIdx.x;
    int idx = blockIdx.x * 1024 + t;
    int v = (idx < Nn) ? g_deg[idx] : 0;
    sh[t] = v;
    for (int ofs = 1; ofs < 1024; ofs <<= 1) {
        __syncthreads();
        int add = (t >= ofs) ? sh[t - ofs] : 0;
        __syncthreads();
        sh[t] += add;
    }
    __syncthreads();
    if (idx < Nn) g_rowptr[idx] = sh[t] - v;   // block-local exclusive
    if (t == 1023) g_bsum[blockIdx.x] = sh[1023];
}

// merged scan2+scan3: every block redundantly scans the <=128 block sums
__global__ void k_scan23(int nblk) {
    __shared__ int sp[128];
    int t = threadIdx.x;
    if (t < 128) sp[t] = (t < nblk) ? g_bsum[t] : 0;
    __syncthreads();
    for (int ofs = 1; ofs < 128; ofs <<= 1) {
        int add = 0;
        if (t < 128 && t >= ofs) add = sp[t - ofs];
        __syncthreads();
        if (t < 128) sp[t] += add;
        __syncthreads();
    }
    int b = blockIdx.x;
    int off = sp[b] - ((b < nblk) ? g_bsum[b] : 0);
    int idx = b * 1024 + t;
    if (idx < Nn) g_rowptr[idx] += off;
    if (idx == Nn) g_rowptr[Nn] = Ee;
}

__global__ void k_fill(const int* __restrict__ edge) {
    int e = blockIdx.x * blockDim.x + threadIdx.x;
    if (e >= Ee) return;
    int d = edge[Ee + e];
    int pos = g_rowptr[d] + atomicAdd(&g_rowfill[d], 1);
    g_col[pos] = edge[e];
}

// ---------------- mean aggregation: warp per node, 4-way pipelined gather ----------------
__global__ void k_agg(const float* __restrict__ h, uint32_t* __restrict__ agp) {
    int gw   = (blockIdx.x * blockDim.x + threadIdx.x) >> 5;
    int lane = threadIdx.x & 31;
    if (gw >= Nn) return;
    int beg = g_rowptr[gw], end = g_rowptr[gw + 1];
    float4 aA = make_float4(0.f, 0.f, 0.f, 0.f);
    float4 aB = make_float4(0.f, 0.f, 0.f, 0.f);
    int e = beg;
    for (; e + 4 <= end; e += 4) {
        int s0 = __ldg(&g_col[e]);
        int s1 = __ldg(&g_col[e + 1]);
        int s2 = __ldg(&g_col[e + 2]);
        int s3 = __ldg(&g_col[e + 3]);
        float4 v0 = __ldg((const float4*)(h + (size_t)s0 * Hh) + lane);
        float4 v1 = __ldg((const float4*)(h + (size_t)s1 * Hh) + lane);
        float4 v2 = __ldg((const float4*)(h + (size_t)s2 * Hh) + lane);
        float4 v3 = __ldg((const float4*)(h + (size_t)s3 * Hh) + lane);
        aA.x += v0.x; aA.y += v0.y; aA.z += v0.z; aA.w += v0.w;
        aB.x += v1.x; aB.y += v1.y; aB.z += v1.z; aB.w += v1.w;
        aA.x += v2.x; aA.y += v2.y; aA.z += v2.z; aA.w += v2.w;
        aB.x += v3.x; aB.y += v3.y; aB.z += v3.z; aB.w += v3.w;
    }
    for (; e < end; e++) {
        int s = __ldg(&g_col[e]);
        float4 v = __ldg((const float4*)(h + (size_t)s * Hh) + lane);
        aA.x += v.x; aA.y += v.y; aA.z += v.z; aA.w += v.w;
    }
    float inv = 1.0f / fmaxf((float)(end - beg), 1.0f);
    uint4 q;
    q.x = packf((aA.x + aB.x) * inv);
    q.y = packf((aA.y + aB.y) * inv);
    q.z = packf((aA.z + aB.z) * inv);
    q.w = packf((aA.w + aB.w) * inv);
    ((uint4*)(agp + (size_t)gw * Hh))[lane] = q;
}

// ---------------- weight prep (all 3 layers): [Wl|Wr] K=256 -> B fragments ----------------
__global__ void k_prepw(const float* __restrict__ Wl1, const float* __restrict__ Wr1,
                        const float* __restrict__ Wl2, const float* __restrict__ Wr2,
                        const float* __restrict__ Wl3, const float* __restrict__ Wr3) {
    int idx = blockIdx.x * blockDim.x + threadIdx.x;
    if (idx >= 3 * 8192) return;
    int L = idx >> 13, id = idx & 8191;
    const float* Wl = (L == 0) ? Wl1 : (L == 1) ? Wl2 : Wl3;
    const float* Wr = (L == 0) ? Wr1 : (L == 1) ? Wr2 : Wr3;
    int lane = id & 31, ks = (id >> 5) & 15, nt = id >> 9;
    int o = nt * 8 + (lane >> 2);
    int kb = ks * 16 + 2 * (lane & 3);
    float v[4];
#pragma unroll
    for (int j = 0; j < 4; j++) {
        int k = kb + (j >> 1) * 8 + (j & 1);   // k0, k0+1, k0+8, k0+9
        v[j] = (k < Hh) ? Wl[o * Hh + k] : Wr[o * Hh + (k - Hh)];
    }
    __nv_bfloat16 hb[4]; __nv_bfloat16 lb[4];
#pragma unroll
    for (int j = 0; j < 4; j++) {
        hb[j] = __float2bfloat16(v[j]);
        lb[j] = __float2bfloat16(v[j] - __bfloat162float(hb[j]));
    }
    uint4 q;
    q.x = pack_bf16(hb[0], hb[1]);
    q.y = pack_bf16(hb[2], hb[3]);
    q.z = pack_bf16(lb[0], lb[1]);
    q.w = pack_bf16(lb[2], lb[3]);
    g_wfrag[idx] = q;
}

// ---------------- mma.sync fused dual GEMM + LN + ReLU, M=256 tile ----------------
#define GSMEM (8192 * 16 + 3 * 512)

__global__ void __launch_bounds__(512, 1)
k_gemm_mma(const uint32_t* __restrict__ agp, const uint32_t* __restrict__ hp,
           const uint4* __restrict__ wfrag,
           const float* __restrict__ bl, const float* __restrict__ gg,
           const float* __restrict__ bb,
           float* __restrict__ hf_out, uint32_t* __restrict__ hp_out,
           float* __restrict__ f32_out, int mode)
{
    extern __shared__ char smc[];
    uint4* sB    = (uint4*)smc;                       // 8192 uint4 = 128 KB
    float* sBias = (float*)(smc + 8192 * 16);
    float* sG    = sBias + 128;
    float* sBb   = sG + 128;

    int tid = threadIdx.x, lane = tid & 31, warp = tid >> 5;
    int nb = blockIdx.x * 256;

#pragma unroll
    for (int i = 0; i < 16; i++) sB[tid + i * 512] = wfrag[tid + i * 512];
    if (tid < 128) { sBias[tid] = bl[tid]; sG[tid] = gg[tid]; sBb[tid] = bb[tid]; }
    __syncthreads();

    int r0    = warp * 16 + (lane >> 2);
    int grow0 = nb + r0, grow1 = grow0 + 8;
    bool v0 = grow0 < Nn, v1 = grow1 < Nn;
    int kcol = 2 * (lane & 3);

    float acc[16][4];
#pragma unroll
    for (int nt = 0; nt < 16; nt++) {
        acc[nt][0] = 0.f; acc[nt][1] = 0.f; acc[nt][2] = 0.f; acc[nt][3] = 0.f;
    }

    const uint2 z2 = make_uint2(0u, 0u);
#pragma unroll 4
    for (int ks = 0; ks < 16; ks++) {
        const uint32_t* pp = (ks < 8) ? agp : hp;
        int ko = (ks & 7) * 16 + kcol;
        const uint32_t* r0p = pp + (size_t)grow0 * Hh + ko;
        const uint32_t* r1p = pp + (size_t)grow1 * Hh + ko;
        uint2 p00 = v0 ? __ldg((const uint2*)r0p)       : z2;
        uint2 p02 = v0 ? __ldg((const uint2*)(r0p + 8)) : z2;
        uint2 p10 = v1 ? __ldg((const uint2*)r1p)       : z2;
        uint2 p12 = v1 ? __ldg((const uint2*)(r1p + 8)) : z2;
        uint32_t ah[4], al[4];
        ah[0] = __byte_perm(p00.x, p00.y, 0x7632); al[0] = __byte_perm(p00.x, p00.y, 0x5410);
        ah[1] = __byte_perm(p10.x, p10.y, 0x7632); al[1] = __byte_perm(p10.x, p10.y, 0x5410);
        ah[2] = __byte_perm(p02.x, p02.y, 0x7632); al[2] = __byte_perm(p02.x, p02.y, 0x5410);
        ah[3] = __byte_perm(p12.x, p12.y, 0x7632); al[3] = __byte_perm(p12.x, p12.y, 0x5410);
        const uint4* brow = sB + ks * 32 + lane;
#pragma unroll
        for (int nt = 0; nt < 16; nt++) {
            uint4 b = brow[nt * 512];
            mma16816(acc[nt], ah, b.x, b.y);   // Ah * Wh
            mma16816(acc[nt], al, b.x, b.y);   // Al * Wh
            mma16816(acc[nt], ah, b.z, b.w);   // Ah * Wl
        }
    }

    // ---- epilogue: bias + LN + ReLU ----
    float s0 = 0.f, q0 = 0.f, s1 = 0.f, q1 = 0.f;
#pragma unroll
    for (int nt = 0; nt < 16; nt++) {
        int c = nt * 8 + kcol;
        float b0v = sBias[c], b1v = sBias[c + 1];
        acc[nt][0] += b0v; acc[nt][1] += b1v;
        acc[nt][2] += b0v; acc[nt][3] += b1v;
        s0 += acc[nt][0] + acc[nt][1];
        q0 += acc[nt][0] * acc[nt][0] + acc[nt][1] * acc[nt][1];
        s1 += acc[nt][2] + acc[nt][3];
        q1 += acc[nt][2] * acc[nt][2] + acc[nt][3] * acc[nt][3];
    }
#pragma unroll
    for (int ofs = 1; ofs <= 2; ofs <<= 1) {
        s0 += __shfl_xor_sync(0xffffffffu, s0, ofs);
        q0 += __shfl_xor_sync(0xffffffffu, q0, ofs);
        s1 += __shfl_xor_sync(0xffffffffu, s1, ofs);
        q1 += __shfl_xor_sync(0xffffffffu, q1, ofs);
    }
    float mean0 = s0 * (1.f / Hh);
    float rstd0 = rsqrtf(q0 * (1.f / Hh) - mean0 * mean0 + EPSv);
    float mean1 = s1 * (1.f / Hh);
    float rstd1 = rsqrtf(q1 * (1.f / Hh) - mean1 * mean1 + EPSv);

#pragma unroll
    for (int nt = 0; nt < 16; nt++) {
        int c = nt * 8 + kcol;
        float gc0 = sG[c], gc1 = sG[c + 1], bc0 = sBb[c], bc1 = sBb[c + 1];
        float w0 = fmaxf((acc[nt][0] - mean0) * rstd0 * gc0 + bc0, 0.f);
        float w1 = fmaxf((acc[nt][1] - mean0) * rstd0 * gc1 + bc1, 0.f);
        float w2 = fmaxf((acc[nt][2] - mean1) * rstd1 * gc0 + bc0, 0.f);
        float w3 = fmaxf((acc[nt][3] - mean1) * rstd1 * gc1 + bc1, 0.f);
        if (mode == 0) {
            if (v0) {
                *(float2*)(hf_out + (size_t)grow0 * Hh + c) = make_float2(w0, w1);
                *(uint2*)(hp_out + (size_t)grow0 * Hh + c) = make_uint2(packf(w0), packf(w1));
            }
            if (v1) {
                *(float2*)(hf_out + (size_t)grow1 * Hh + c) = make_float2(w2, w3);
                *(uint2*)(hp_out + (size_t)grow1 * Hh + c) = make_uint2(packf(w2), packf(w3));
            }
        } else {
            if (v0) *(float2*)(f32_out + (size_t)grow0 * Hh + c) = make_float2(w0, w1);
            if (v1) *(float2*)(f32_out + (size_t)grow1 * Hh + c) = make_float2(w2, w3);
        }
    }
}

// ---------------- pooling ----------------
#define PT 256
__global__ void k_pool(const float* __restrict__ ne, const int* __restrict__ batch) {
    __shared__ int sbk[PT];
    int c = threadIdx.x;
    int start = blockIdx.x * PT;
    int cnt_nodes = min(PT, Nn - start);
    for (int i = c; i < cnt_nodes; i += 128) sbk[i] = batch[start + i];
    __syncthreads();
    float s = 0.f, mx = 0.f; int cnt = 0;
    int curb = sbk[0];
    for (int i = 0; i < cnt_nodes; i++) {
        int b = sbk[i];
        if (b != curb) {
            atomicAdd(&g_psum[curb * Hh + c], s);
            atomicMax(&g_pmax[curb * Hh + c], __float_as_int(mx));
            if (c == 0) atomicAdd(&g_pcnt[curb], cnt);
            s = 0.f; mx = 0.f; cnt = 0; curb = b;
        }
        float v = ne[(size_t)(start + i) * Hh + c];
        s += v; mx = fmaxf(mx, v); cnt++;
    }
    atomicAdd(&g_psum[curb * Hh + c], s);
    atomicMax(&g_pmax[curb * Hh + c], __float_as_int(mx));
    if (c == 0) atomicAdd(&g_pcnt[curb], cnt);
}

__global__ void k_pool_fin(float* __restrict__ out) {
    int idx = blockIdx.x * blockDim.x + threadIdx.x;
    if (idx >= Bb * Hh) return;
    int b = idx >> 7, c = idx & 127;
    float cnt = fmaxf((float)g_pcnt[b], 1.f);
    out[(size_t)Nn * Hh + b * 2 * Hh + c]      = g_psum[idx] / cnt;
    out[(size_t)Nn * Hh + b * 2 * Hh + Hh + c] = __int_as_float(g_pmax[idx]);
}

// ---------------- launch ----------------
extern "C" void kernel_launch(void* const* d_in, const int* in_sizes, int n_in,
                              void* d_out, int out_size) {
    const float* x    = (const float*)d_in[0];
    const int*   edge = (const int*)  d_in[1];
    const int*   batch= (const int*)  d_in[2];
    const float* W0   = (const float*)d_in[3];
    const float* b0   = (const float*)d_in[4];
    const float* g0   = (const float*)d_in[5];
    const float* be0  = (const float*)d_in[6];
    const float* Wl1  = (const float*)d_in[7];
    const float* bl1  = (const float*)d_in[8];
    const float* Wr1  = (const float*)d_in[9];
    const float* g1   = (const float*)d_in[10];
    const float* be1  = (const float*)d_in[11];
    const float* Wl2  = (const float*)d_in[12];
    const float* bl2  = (const float*)d_in[13];
    const float* Wr2  = (const float*)d_in[14];
    const float* g2   = (const float*)d_in[15];
    const float* be2  = (const float*)d_in[16];
    const float* Wl3  = (const float*)d_in[17];
    const float* bl3  = (const float*)d_in[18];
    const float* Wr3  = (const float*)d_in[19];
    const float* g3   = (const float*)d_in[20];
    const float* be3  = (const float*)d_in[21];
    float* out = (float*)d_out;

    static int attr_set = 0;
    if (!attr_set) {
        cudaFuncSetAttribute(k_gemm_mma, cudaFuncAttributeMaxDynamicSharedMemorySize, GSMEM);
        attr_set = 1;
    }

    float* hA = 0;
    float* hB = 0;
    uint32_t* hp0 = 0;
    uint32_t* hp1 = 0;
    uint32_t* agp = 0;
    uint4* wf = 0;
    cudaGetSymbolAddress((void**)&hA, g_h);
    cudaGetSymbolAddress((void**)&hB, g_h2);
    cudaGetSymbolAddress((void**)&hp0, g_hp0);
    cudaGetSymbolAddress((void**)&hp1, g_hp1);
    cudaGetSymbolAddress((void**)&agp, g_agp);
    cudaGetSymbolAddress((void**)&wf, g_wfrag);

    int nblkScan = (Nn + 1023) / 1024;
    int gemmGrid = (Nn + 255) / 256;
    int aggGrid  = (Nn * 32 + 255) / 256;
    int prepGrid = (3 * 8192 + 255) / 256;

    // launches 0-4: embed(+init), CSR build
    k_embed <<<Nn, 128>>>(x, W0, b0, g0, be0, hp0);
    k_degree<<<(Ee + 255) / 256, 256>>>(edge);
    k_scan1 <<<nblkScan, 1024>>>();
    k_scan23<<<nblkScan, 1024>>>(nblkScan);
    k_fill  <<<(Ee + 255) / 256, 256>>>(edge);

    // launch 5 = k_agg (ncu -s 5 profiles this one)
    k_agg   <<<aggGrid, 256>>>(hA, agp);
    k_prepw <<<prepGrid, 256>>>(Wl1, Wr1, Wl2, Wr2, Wl3, Wr3);

    // layer 1: (agp, hp0) -> hB/hp1
    k_gemm_mma<<<gemmGrid, 512, GSMEM>>>(agp, hp0, wf,
                                         bl1, g1, be1, hB, hp1, (float*)0, 0);
    // layer 2: (agp, hp1) -> hA/hp0
    k_agg   <<<aggGrid, 256>>>(hB, agp);
    k_gemm_mma<<<gemmGrid, 512, GSMEM>>>(agp, hp1, wf + 8192,
                                         bl2, g2, be2, hA, hp0, (float*)0, 0);
    // layer 3: (agp, hp0) -> out fp32
    k_agg   <<<aggGrid, 256>>>(hA, agp);
    k_gemm_mma<<<gemmGrid, 512, GSMEM>>>(agp, hp0, wf + 16384,
                                         bl3, g3, be3, (float*)0, (uint32_t*)0, out, 1);

    k_pool    <<<(Nn + PT - 1) / PT, 128>>>(out, batch);
    k_pool_fin<<<(Bb * Hh + 127) / 128, 128>>>(out);
}

// round 8
// speedup vs baseline: 1.8117x; 1.0838x over previous
#include <cuda_runtime.h>
#include <cuda_bf16.h>
#include <cuda_fp16.h>
#include <cstdint>

#define Nn   100000
#define Ee   1600000
#define Bb   64
#define DINc 9
#define Hh   128
#define EPSv 1e-5f

// ---------------- device scratch ----------------
__device__ __half   g_hh [Nn * Hh];      // half features (agg gather source)
__device__ uint32_t g_hp0[Nn * Hh];      // packed (bf16hi<<16)|bf16lo  (GEMM root operand)
__device__ uint32_t g_hp1[Nn * Hh];
__device__ uint32_t g_agp[Nn * Hh];      // packed aggregated (GEMM agg operand)
__device__ uint4    g_wfrag[3 * 8192];   // per-layer mma B fragments
__device__ int      g_deg[Nn];
__device__ int      g_rowptr[Nn + 1];
__device__ int      g_rowfill[Nn];
__device__ int      g_col[Ee];
__device__ int      g_bsum[128];
__device__ float    g_psum[Bb * Hh];
__device__ int      g_pmax[Bb * Hh];
__device__ int      g_pcnt[Bb];

// ---------------- helpers ----------------
__device__ __forceinline__ uint32_t packf(float v) {
    __nv_bfloat16 hb = __float2bfloat16(v);
    __nv_bfloat16 lb = __float2bfloat16(v - __bfloat162float(hb));
    return ((uint32_t)__bfloat16_as_ushort(hb) << 16) | (uint32_t)__bfloat16_as_ushort(lb);
}
__device__ __forceinline__ uint32_t pack_bf16(__nv_bfloat16 a, __nv_bfloat16 b) {
    return (uint32_t)__bfloat16_as_ushort(a) | ((uint32_t)__bfloat16_as_ushort(b) << 16);
}
__device__ __forceinline__ void mma16816(float* d, const uint32_t* a, uint32_t b0, uint32_t b1) {
    asm volatile("mma.sync.aligned.m16n8k16.row.col.f32.bf16.bf16.f32 "
        "{%0,%1,%2,%3}, {%4,%5,%6,%7}, {%8,%9}, {%0,%1,%2,%3};"
        : "+f"(d[0]), "+f"(d[1]), "+f"(d[2]), "+f"(d[3])
        : "r"(a[0]), "r"(a[1]), "r"(a[2]), "r"(a[3]), "r"(b0), "r"(b1));
}
// accumulate 4 halves (one uint2) into float4
__device__ __forceinline__ void acc_h4(float4& a, uint2 u) {
    __half2 p0 = *reinterpret_cast<const __half2*>(&u.x);
    __half2 p1 = *reinterpret_cast<const __half2*>(&u.y);
    float2 f0 = __half22float2(p0);
    float2 f1 = __half22float2(p1);
    a.x += f0.x; a.y += f0.y; a.z += f1.x; a.w += f1.y;
}

// ---------------- node embedder (+ global init fused) ----------------
__global__ void k_embed(const float* __restrict__ x, const float* __restrict__ W0,
                        const float* __restrict__ b0, const float* __restrict__ g0,
                        const float* __restrict__ be0, uint32_t* __restrict__ hp) {
    int n = blockIdx.x;
    int o = threadIdx.x;
    int gid = n * 128 + o;
    if (gid < Nn) { g_deg[gid] = 0; g_rowfill[gid] = 0; }
    if (gid < Bb * Hh) { g_psum[gid] = 0.f; g_pmax[gid] = 0; }
    if (gid < Bb) g_pcnt[gid] = 0;

    __shared__ float sx[DINc];
    if (o < DINc) sx[o] = x[n * DINc + o];
    __syncthreads();
    float acc = b0[o];
#pragma unroll
    for (int k = 0; k < DINc; k++) acc += W0[o * DINc + k] * sx[k];

    float s = acc, sq = acc * acc;
#pragma unroll
    for (int ofs = 16; ofs > 0; ofs >>= 1) {
        s  += __shfl_xor_sync(0xffffffffu, s,  ofs);
        sq += __shfl_xor_sync(0xffffffffu, sq, ofs);
    }
    __shared__ float rs[4], rq[4];
    int w = o >> 5, lane = o & 31;
    if (lane == 0) { rs[w] = s; rq[w] = sq; }
    __syncthreads();
    s  = rs[0] + rs[1] + rs[2] + rs[3];
    sq = rq[0] + rq[1] + rq[2] + rq[3];
    float mean = s * (1.f / Hh);
    float var  = sq * (1.f / Hh) - mean * mean;
    float rstd = rsqrtf(var + EPSv);
    float v = (acc - mean) * rstd * g0[o] + be0[o];
    float r = fmaxf(v, 0.f);
    size_t idx = (size_t)n * Hh + o;
    g_hh[idx] = __float2half_rn(r);
    hp[idx] = packf(r);
}

// ---------------- CSR build ----------------
__global__ void k_degree(const int* __restrict__ edge) {
    int e = blockIdx.x * blockDim.x + threadIdx.x;
    if (e >= Ee) return;
    atomicAdd(&g_deg[edge[Ee + e]], 1);
}

__global__ void k_scan1() {
    __shared__ int sh[1024];
    int t = threadIdx.x;
    int idx = blockIdx.x * 1024 + t;
    int v = (idx < Nn) ? g_deg[idx] : 0;
    sh[t] = v;
    for (int ofs = 1; ofs < 1024; ofs <<= 1) {
        __syncthreads();
        int add = (t >= ofs) ? sh[t - ofs] : 0;
        __syncthreads();
        sh[t] += add;
    }
    __syncthreads();
    if (idx < Nn) g_rowptr[idx] = sh[t] - v;   // block-local exclusive
    if (t == 1023) g_bsum[blockIdx.x] = sh[1023];
}

// merged scan2+scan3: every block redundantly scans the <=128 block sums
__global__ void k_scan23(int nblk) {
    __shared__ int sp[128];
    int t = threadIdx.x;
    if (t < 128) sp[t] = (t < nblk) ? g_bsum[t] : 0;
    __syncthreads();
    for (int ofs = 1; ofs < 128; ofs <<= 1) {
        int add = 0;
        if (t < 128 && t >= ofs) add = sp[t - ofs];
        __syncthreads();
        if (t < 128) sp[t] += add;
        __syncthreads();
    }
    int b = blockIdx.x;
    int off = sp[b] - ((b < nblk) ? g_bsum[b] : 0);
    int idx = b * 1024 + t;
    if (idx < Nn) g_rowptr[idx] += off;
    if (idx == Nn) g_rowptr[Nn] = Ee;
}

__global__ void k_fill(const int* __restrict__ edge) {
    int e = blockIdx.x * blockDim.x + threadIdx.x;
    if (e >= Ee) return;
    int d = edge[Ee + e];
    int pos = g_rowptr[d] + atomicAdd(&g_rowfill[d], 1);
    g_col[pos] = edge[e];
}

// ---------------- mean aggregation: warp per node, half rows (256 B), 4-way pipelined ----------------
__global__ void k_agg(const __half* __restrict__ hh, uint32_t* __restrict__ agp) {
    int gw   = (blockIdx.x * blockDim.x + threadIdx.x) >> 5;
    int lane = threadIdx.x & 31;
    if (gw >= Nn) return;
    int beg = g_rowptr[gw], end = g_rowptr[gw + 1];
    float4 aA = make_float4(0.f, 0.f, 0.f, 0.f);
    float4 aB = make_float4(0.f, 0.f, 0.f, 0.f);
    int e = beg;
    for (; e + 4 <= end; e += 4) {
        int s0 = __ldg(&g_col[e]);
        int s1 = __ldg(&g_col[e + 1]);
        int s2 = __ldg(&g_col[e + 2]);
        int s3 = __ldg(&g_col[e + 3]);
        uint2 u0 = __ldg((const uint2*)(hh + (size_t)s0 * Hh) + lane);
        uint2 u1 = __ldg((const uint2*)(hh + (size_t)s1 * Hh) + lane);
        uint2 u2 = __ldg((const uint2*)(hh + (size_t)s2 * Hh) + lane);
        uint2 u3 = __ldg((const uint2*)(hh + (size_t)s3 * Hh) + lane);
        acc_h4(aA, u0);
        acc_h4(aB, u1);
        acc_h4(aA, u2);
        acc_h4(aB, u3);
    }
    for (; e < end; e++) {
        int s = __ldg(&g_col[e]);
        uint2 u = __ldg((const uint2*)(hh + (size_t)s * Hh) + lane);
        acc_h4(aA, u);
    }
    float inv = 1.0f / fmaxf((float)(end - beg), 1.0f);
    uint4 q;
    q.x = packf((aA.x + aB.x) * inv);
    q.y = packf((aA.y + aB.y) * inv);
    q.z = packf((aA.z + aB.z) * inv);
    q.w = packf((aA.w + aB.w) * inv);
    ((uint4*)(agp + (size_t)gw * Hh))[lane] = q;
}

// ---------------- weight prep (all 3 layers): [Wl|Wr] K=256 -> B fragments ----------------
__global__ void k_prepw(const float* __restrict__ Wl1, const float* __restrict__ Wr1,
                        const float* __restrict__ Wl2, const float* __restrict__ Wr2,
                        const float* __restrict__ Wl3, const float* __restrict__ Wr3) {
    int idx = blockIdx.x * blockDim.x + threadIdx.x;
    if (idx >= 3 * 8192) return;
    int L = idx >> 13, id = idx & 8191;
    const float* Wl = (L == 0) ? Wl1 : (L == 1) ? Wl2 : Wl3;
    const float* Wr = (L == 0) ? Wr1 : (L == 1) ? Wr2 : Wr3;
    int lane = id & 31, ks = (id >> 5) & 15, nt = id >> 9;
    int o = nt * 8 + (lane >> 2);
    int kb = ks * 16 + 2 * (lane & 3);
    float v[4];
#pragma unroll
    for (int j = 0; j < 4; j++) {
        int k = kb + (j >> 1) * 8 + (j & 1);   // k0, k0+1, k0+8, k0+9
        v[j] = (k < Hh) ? Wl[o * Hh + k] : Wr[o * Hh + (k - Hh)];
    }
    __nv_bfloat16 hb[4]; __nv_bfloat16 lb[4];
#pragma unroll
    for (int j = 0; j < 4; j++) {
        hb[j] = __float2bfloat16(v[j]);
        lb[j] = __float2bfloat16(v[j] - __bfloat162float(hb[j]));
    }
    uint4 q;
    q.x = pack_bf16(hb[0], hb[1]);
    q.y = pack_bf16(hb[2], hb[3]);
    q.z = pack_bf16(lb[0], lb[1]);
    q.w = pack_bf16(lb[2], lb[3]);
    g_wfrag[idx] = q;
}

// ---------------- mma.sync fused dual GEMM + LN + ReLU, M=256 tile ----------------
#define GSMEM (8192 * 16 + 3 * 512)

__global__ void __launch_bounds__(512, 1)
k_gemm_mma(const uint32_t* __restrict__ agp, const uint32_t* __restrict__ hp,
           const uint4* __restrict__ wfrag,
           const float* __restrict__ bl, const float* __restrict__ gg,
           const float* __restrict__ bb,
           __half* __restrict__ hh_out, uint32_t* __restrict__ hp_out,
           float* __restrict__ f32_out, int mode)
{
    extern __shared__ char smc[];
    uint4* sB    = (uint4*)smc;                       // 8192 uint4 = 128 KB
    float* sBias = (float*)(smc + 8192 * 16);
    float* sG    = sBias + 128;
    float* sBb   = sG + 128;

    int tid = threadIdx.x, lane = tid & 31, warp = tid >> 5;
    int nb = blockIdx.x * 256;

#pragma unroll
    for (int i = 0; i < 16; i++) sB[tid + i * 512] = wfrag[tid + i * 512];
    if (tid < 128) { sBias[tid] = bl[tid]; sG[tid] = gg[tid]; sBb[tid] = bb[tid]; }
    __syncthreads();

    int r0    = warp * 16 + (lane >> 2);
    int grow0 = nb + r0, grow1 = grow0 + 8;
    bool v0 = grow0 < Nn, v1 = grow1 < Nn;
    int kcol = 2 * (lane & 3);

    float acc[16][4];
#pragma unroll
    for (int nt = 0; nt < 16; nt++) {
        acc[nt][0] = 0.f; acc[nt][1] = 0.f; acc[nt][2] = 0.f; acc[nt][3] = 0.f;
    }

    const uint2 z2 = make_uint2(0u, 0u);
#pragma unroll 4
    for (int ks = 0; ks < 16; ks++) {
        const uint32_t* pp = (ks < 8) ? agp : hp;
        int ko = (ks & 7) * 16 + kcol;
        const uint32_t* r0p = pp + (size_t)grow0 * Hh + ko;
        const uint32_t* r1p = pp + (size_t)grow1 * Hh + ko;
        uint2 p00 = v0 ? __ldg((const uint2*)r0p)       : z2;
        uint2 p02 = v0 ? __ldg((const uint2*)(r0p + 8)) : z2;
        uint2 p10 = v1 ? __ldg((const uint2*)r1p)       : z2;
        uint2 p12 = v1 ? __ldg((const uint2*)(r1p + 8)) : z2;
        uint32_t ah[4], al[4];
        ah[0] = __byte_perm(p00.x, p00.y, 0x7632); al[0] = __byte_perm(p00.x, p00.y, 0x5410);
        ah[1] = __byte_perm(p10.x, p10.y, 0x7632); al[1] = __byte_perm(p10.x, p10.y, 0x5410);
        ah[2] = __byte_perm(p02.x, p02.y, 0x7632); al[2] = __byte_perm(p02.x, p02.y, 0x5410);
        ah[3] = __byte_perm(p12.x, p12.y, 0x7632); al[3] = __byte_perm(p12.x, p12.y, 0x5410);
        const uint4* brow = sB + ks * 32 + lane;
#pragma unroll
        for (int nt = 0; nt < 16; nt++) {
            uint4 b = brow[nt * 512];
            mma16816(acc[nt], ah, b.x, b.y);   // Ah * Wh
            mma16816(acc[nt], al, b.x, b.y);   // Al * Wh
            mma16816(acc[nt], ah, b.z, b.w);   // Ah * Wl
        }
    }

    // ---- epilogue: bias + LN + ReLU ----
    float s0 = 0.f, q0 = 0.f, s1 = 0.f, q1 = 0.f;
#pragma unroll
    for (int nt = 0; nt < 16; nt++) {
        int c = nt * 8 + kcol;
        float b0v = sBias[c], b1v = sBias[c + 1];
        acc[nt][0] += b0v; acc[nt][1] += b1v;
        acc[nt][2] += b0v; acc[nt][3] += b1v;
        s0 += acc[nt][0] + acc[nt][1];
        q0 += acc[nt][0] * acc[nt][0] + acc[nt][1] * acc[nt][1];
        s1 += acc[nt][2] + acc[nt][3];
        q1 += acc[nt][2] * acc[nt][2] + acc[nt][3] * acc[nt][3];
    }
#pragma unroll
    for (int ofs = 1; ofs <= 2; ofs <<= 1) {
        s0 += __shfl_xor_sync(0xffffffffu, s0, ofs);
        q0 += __shfl_xor_sync(0xffffffffu, q0, ofs);
        s1 += __shfl_xor_sync(0xffffffffu, s1, ofs);
        q1 += __shfl_xor_sync(0xffffffffu, q1, ofs);
    }
    float mean0 = s0 * (1.f / Hh);
    float rstd0 = rsqrtf(q0 * (1.f / Hh) - mean0 * mean0 + EPSv);
    float mean1 = s1 * (1.f / Hh);
    float rstd1 = rsqrtf(q1 * (1.f / Hh) - mean1 * mean1 + EPSv);

#pragma unroll
    for (int nt = 0; nt < 16; nt++) {
        int c = nt * 8 + kcol;
        float gc0 = sG[c], gc1 = sG[c + 1], bc0 = sBb[c], bc1 = sBb[c + 1];
        float w0 = fmaxf((acc[nt][0] - mean0) * rstd0 * gc0 + bc0, 0.f);
        float w1 = fmaxf((acc[nt][1] - mean0) * rstd0 * gc1 + bc1, 0.f);
        float w2 = fmaxf((acc[nt][2] - mean1) * rstd1 * gc0 + bc0, 0.f);
        float w3 = fmaxf((acc[nt][3] - mean1) * rstd1 * gc1 + bc1, 0.f);
        if (mode == 0) {
            if (v0) {
                __half2 hw; hw.x = __float2half_rn(w0); hw.y = __float2half_rn(w1);
                *(__half2*)(hh_out + (size_t)grow0 * Hh + c) = hw;
                *(uint2*)(hp_out + (size_t)grow0 * Hh + c) = make_uint2(packf(w0), packf(w1));
            }
            if (v1) {
                __half2 hw; hw.x = __float2half_rn(w2); hw.y = __float2half_rn(w3);
                *(__half2*)(hh_out + (size_t)grow1 * Hh + c) = hw;
                *(uint2*)(hp_out + (size_t)grow1 * Hh + c) = make_uint2(packf(w2), packf(w3));
            }
        } else {
            if (v0) *(float2*)(f32_out + (size_t)grow0 * Hh + c) = make_float2(w0, w1);
            if (v1) *(float2*)(f32_out + (size_t)grow1 * Hh + c) = make_float2(w2, w3);
        }
    }
}

// ---------------- pooling ----------------
#define PT 256
__global__ void k_pool(const float* __restrict__ ne, const int* __restrict__ batch) {
    __shared__ int sbk[PT];
    int c = threadIdx.x;
    int start = blockIdx.x * PT;
    int cnt_nodes = min(PT, Nn - start);
    for (int i = c; i < cnt_nodes; i += 128) sbk[i] = batch[start + i];
    __syncthreads();
    float s = 0.f, mx = 0.f; int cnt = 0;
    int curb = sbk[0];
    for (int i = 0; i < cnt_nodes; i++) {
        int b = sbk[i];
        if (b != curb) {
            atomicAdd(&g_psum[curb * Hh + c], s);
            atomicMax(&g_pmax[curb * Hh + c], __float_as_int(mx));
            if (c == 0) atomicAdd(&g_pcnt[curb], cnt);
            s = 0.f; mx = 0.f; cnt = 0; curb = b;
        }
        float v = ne[(size_t)(start + i) * Hh + c];
        s += v; mx = fmaxf(mx, v); cnt++;
    }
    atomicAdd(&g_psum[curb * Hh + c], s);
    atomicMax(&g_pmax[curb * Hh + c], __float_as_int(mx));
    if (c == 0) atomicAdd(&g_pcnt[curb], cnt);
}

__global__ void k_pool_fin(float* __restrict__ out) {
    int idx = blockIdx.x * blockDim.x + threadIdx.x;
    if (idx >= Bb * Hh) return;
    int b = idx >> 7, c = idx & 127;
    float cnt = fmaxf((float)g_pcnt[b], 1.f);
    out[(size_t)Nn * Hh + b * 2 * Hh + c]      = g_psum[idx] / cnt;
    out[(size_t)Nn * Hh + b * 2 * Hh + Hh + c] = __int_as_float(g_pmax[idx]);
}

// ---------------- launch ----------------
extern "C" void kernel_launch(void* const* d_in, const int* in_sizes, int n_in,
                              void* d_out, int out_size) {
    const float* x    = (const float*)d_in[0];
    const int*   edge = (const int*)  d_in[1];
    const int*   batch= (const int*)  d_in[2];
    const float* W0   = (const float*)d_in[3];
    const float* b0   = (const float*)d_in[4];
    const float* g0   = (const float*)d_in[5];
    const float* be0  = (const float*)d_in[6];
    const float* Wl1  = (const float*)d_in[7];
    const float* bl1  = (const float*)d_in[8];
    const float* Wr1  = (const float*)d_in[9];
    const float* g1   = (const float*)d_in[10];
    const float* be1  = (const float*)d_in[11];
    const float* Wl2  = (const float*)d_in[12];
    const float* bl2  = (const float*)d_in[13];
    const float* Wr2  = (const float*)d_in[14];
    const float* g2   = (const float*)d_in[15];
    const float* be2  = (const float*)d_in[16];
    const float* Wl3  = (const float*)d_in[17];
    const float* bl3  = (const float*)d_in[18];
    const float* Wr3  = (const float*)d_in[19];
    const float* g3   = (const float*)d_in[20];
    const float* be3  = (const float*)d_in[21];
    float* out = (float*)d_out;

    static int attr_set = 0;
    if (!attr_set) {
        cudaFuncSetAttribute(k_gemm_mma, cudaFuncAttributeMaxDynamicSharedMemorySize, GSMEM);
        attr_set = 1;
    }

    __half* hh = 0;
    uint32_t* hp0 = 0;
    uint32_t* hp1 = 0;
    uint32_t* agp = 0;
    uint4* wf = 0;
    cudaGetSymbolAddress((void**)&hh, g_hh);
    cudaGetSymbolAddress((void**)&hp0, g_hp0);
    cudaGetSymbolAddress((void**)&hp1, g_hp1);
    cudaGetSymbolAddress((void**)&agp, g_agp);
    cudaGetSymbolAddress((void**)&wf, g_wfrag);

    int nblkScan = (Nn + 1023) / 1024;
    int gemmGrid = (Nn + 255) / 256;
    int aggGrid  = (Nn * 32 + 255) / 256;
    int prepGrid = (3 * 8192 + 255) / 256;

    k_embed <<<Nn, 128>>>(x, W0, b0, g0, be0, hp0);
    k_degree<<<(Ee + 255) / 256, 256>>>(edge);
    k_scan1 <<<nblkScan, 1024>>>();
    k_scan23<<<nblkScan, 1024>>>(nblkScan);
    k_fill  <<<(Ee + 255) / 256, 256>>>(edge);
    k_prepw <<<prepGrid, 256>>>(Wl1, Wr1, Wl2, Wr2, Wl3, Wr3);

    // layer 1: agg(hh) + root hp0 -> hh/hp1
    k_agg   <<<aggGrid, 256>>>(hh, agp);
    k_gemm_mma<<<gemmGrid, 512, GSMEM>>>(agp, hp0, wf,
                                         bl1, g1, be1, hh, hp1, (float*)0, 0);
    // layer 2: agg(hh) + root hp1 -> hh/hp0
    k_agg   <<<aggGrid, 256>>>(hh, agp);
    k_gemm_mma<<<gemmGrid, 512, GSMEM>>>(agp, hp1, wf + 8192,
                                         bl2, g2, be2, hh, hp0, (float*)0, 0);
    // layer 3: agg(hh) + root hp0 -> out fp32
    k_agg   <<<aggGrid, 256>>>(hh, agp);
    k_gemm_mma<<<gemmGrid, 512, GSMEM>>>(agp, hp0, wf + 16384,
                                         bl3, g3, be3, (__half*)0, (uint32_t*)0, out, 1);

    k_pool    <<<(Nn + PT - 1) / PT, 128>>>(out, batch);
    k_pool_fin<<<(Bb * Hh + 127) / 128, 128>>>(out);
}